// round 1
// baseline (speedup 1.0000x reference)
#include <cuda_runtime.h>

// out[n, p] = sum_f matrix[p, f] * nf_perm[n, f]
// nf_perm[n] = (field[b,0], field[b,3], field[b,1], field[b,2]),  b = batch[n]
// N = 2e6 nodes, P = 32. positions input is unused by the reference output.
//
// Layout: 8 lanes cooperate on one node; lane-group q (0..7) computes output
// floats [4q, 4q+4) and writes them as one float4. A warp therefore covers
// 4 nodes and its st.128 instructions write 512 contiguous bytes.

__global__ __launch_bounds__(256) void dgto_kernel(
    const int*    __restrict__ batch,
    const float4* __restrict__ field,   // [n_graphs] rows of 4 floats
    const float4* __restrict__ matrix,  // 32 rows of 4 floats
    float4*       __restrict__ out,     // [n_nodes * 8] float4 (= n_nodes x 32 f32)
    int n_nodes)
{
    __shared__ float4 sm_mat[32];
    int tid = threadIdx.x;
    if (tid < 32) sm_mat[tid] = matrix[tid];
    __syncthreads();

    long long gthread = (long long)blockIdx.x * blockDim.x + tid;
    int node = (int)(gthread >> 3);
    int quad = (int)(gthread & 7);
    if (node >= n_nodes) return;

    int b = __ldg(&batch[node]);
    float4 f = __ldg(&field[b]);
    // permuted node field: (f0, f3, f1, f2)
    float nfp0 = f.x, nfp1 = f.w, nfp2 = f.y, nfp3 = f.z;

    float4 m0 = sm_mat[quad * 4 + 0];
    float4 m1 = sm_mat[quad * 4 + 1];
    float4 m2 = sm_mat[quad * 4 + 2];
    float4 m3 = sm_mat[quad * 4 + 3];

    float4 r;
    r.x = m0.x * nfp0 + m0.y * nfp1 + m0.z * nfp2 + m0.w * nfp3;
    r.y = m1.x * nfp0 + m1.y * nfp1 + m1.z * nfp2 + m1.w * nfp3;
    r.z = m2.x * nfp0 + m2.y * nfp1 + m2.z * nfp2 + m2.w * nfp3;
    r.w = m3.x * nfp0 + m3.y * nfp1 + m3.z * nfp2 + m3.w * nfp3;

    // Streaming store (evict-first): keep the 1.6 MB field table L2-resident.
    __stcs(&out[(size_t)node * 8 + quad], r);
}

extern "C" void kernel_launch(void* const* d_in, const int* in_sizes, int n_in,
                              void* d_out, int out_size)
{
    const int*    batch  = (const int*)d_in[0];
    // d_in[1] = positions (unused by the reference output)
    const float4* field  = (const float4*)d_in[2];
    const float4* matrix = (const float4*)d_in[3];
    float4*       out    = (float4*)d_out;

    int n_nodes = in_sizes[0];                 // element count of batch
    long long total_threads = (long long)n_nodes * 8;
    int block = 256;
    int grid = (int)((total_threads + block - 1) / block);

    dgto_kernel<<<grid, block>>>(batch, field, matrix, out, n_nodes);
}

// round 2
// speedup vs baseline: 2.6780x; 2.6780x over previous
#include <cuda_runtime.h>

// out[n, p] = sum_f matrix[p, f] * nf_perm[n, f]
// nf_perm[n] = (field[b,0], field[b,3], field[b,1], field[b,2]),  b = batch[n]
//
// 8 lanes per node; lane-group q (quad = lane & 7) owns output floats
// [4q, 4q+4) written as one float4 -> each warp's STG.128 covers 512
// contiguous bytes. Persistent grid-stride threads: quad is invariant per
// thread (stride is a multiple of 8), so the 4 matrix rows this thread needs
// live in registers for the whole kernel -- zero shared/matrix traffic in the
// loop (was 16 of 25 L1 wavefronts per warp-iter in R1).

__global__ __launch_bounds__(256) void dgto_kernel(
    const int*    __restrict__ batch,
    const float4* __restrict__ field,   // [n_graphs] rows of 4 floats
    const float4* __restrict__ matrix,  // 32 rows of 4 floats
    float4*       __restrict__ out,     // [n_nodes * 8] float4
    int n_nodes)
{
    const long long total = 8LL * (long long)n_nodes;
    const long long stride = (long long)gridDim.x * blockDim.x;  // multiple of 8
    long long p = (long long)blockIdx.x * blockDim.x + threadIdx.x;

    const int quad = (int)(p & 7);  // invariant across iterations
    const float4 m0 = __ldg(&matrix[quad * 4 + 0]);
    const float4 m1 = __ldg(&matrix[quad * 4 + 1]);
    const float4 m2 = __ldg(&matrix[quad * 4 + 2]);
    const float4 m3 = __ldg(&matrix[quad * 4 + 3]);

    for (; p < total; p += stride) {
        const int node = (int)(p >> 3);
        const int b = __ldg(&batch[node]);
        const float4 f = __ldg(&field[b]);
        // permuted node field: (f0, f3, f1, f2)
        const float nfp0 = f.x, nfp1 = f.w, nfp2 = f.y, nfp3 = f.z;

        float4 r;
        r.x = m0.x * nfp0 + m0.y * nfp1 + m0.z * nfp2 + m0.w * nfp3;
        r.y = m1.x * nfp0 + m1.y * nfp1 + m1.z * nfp2 + m1.w * nfp3;
        r.z = m2.x * nfp0 + m2.y * nfp1 + m2.z * nfp2 + m2.w * nfp3;
        r.w = m3.x * nfp0 + m3.y * nfp1 + m3.z * nfp2 + m3.w * nfp3;

        // Streaming store (evict-first): keep the field table L2-resident.
        __stcs(&out[p], r);
    }
}

extern "C" void kernel_launch(void* const* d_in, const int* in_sizes, int n_in,
                              void* d_out, int out_size)
{
    const int*    batch  = (const int*)d_in[0];
    // d_in[1] = positions (unused by the reference output)
    const float4* field  = (const float4*)d_in[2];
    const float4* matrix = (const float4*)d_in[3];
    float4*       out    = (float4*)d_out;

    int n_nodes = in_sizes[0];

    // Persistent launch: ~full occupancy on 148 SMs (2048 thr/SM / 256 = 8
    // blocks/SM). Grid-stride total is a multiple of 8 (block=256), so each
    // thread's quad is loop-invariant.
    const int block = 256;
    const int grid  = 148 * 8;

    dgto_kernel<<<grid, block>>>(batch, field, matrix, out, n_nodes);
}

// round 3
// speedup vs baseline: 2.6989x; 1.0078x over previous
#include <cuda_runtime.h>

// out[n, p] = sum_f matrix[p, f] * nf_perm[n, f]
// nf_perm[n] = (field[b,0], field[b,3], field[b,1], field[b,2]),  b = batch[n]
//
// 8 lanes per node; lane-group q (quad = lane & 7) owns output floats
// [4q, 4q+4) written as one float4 -> each warp's STG.128 covers 512
// contiguous bytes. Persistent grid-stride threads with quad invariant
// (stride multiple of 8) keep the 4 matrix rows in registers.
// R3: unroll x2 (independent gather chains -> 2x MLP) + 32-bit indexing
// (total = 8*n_nodes = 16M < 2^31) to cut 64-bit IMAD overhead.

__global__ __launch_bounds__(256) void dgto_kernel(
    const int*    __restrict__ batch,
    const float4* __restrict__ field,   // [n_graphs] rows of 4 floats
    const float4* __restrict__ matrix,  // 32 rows of 4 floats
    float4*       __restrict__ out,     // [n_nodes * 8] float4
    int n_nodes)
{
    const int total  = n_nodes * 8;
    const int stride = gridDim.x * blockDim.x;   // multiple of 8
    int p = blockIdx.x * blockDim.x + threadIdx.x;

    const int quad = p & 7;  // loop-invariant
    const float4 m0 = __ldg(&matrix[quad * 4 + 0]);
    const float4 m1 = __ldg(&matrix[quad * 4 + 1]);
    const float4 m2 = __ldg(&matrix[quad * 4 + 2]);
    const float4 m3 = __ldg(&matrix[quad * 4 + 3]);

    // Main unrolled loop: two independent iterations in flight.
    for (; p + stride < total; p += 2 * stride) {
        const int pb = p + stride;
        const int b0 = __ldg(&batch[p  >> 3]);
        const int b1 = __ldg(&batch[pb >> 3]);
        const float4 f0 = __ldg(&field[b0]);
        const float4 f1 = __ldg(&field[b1]);

        // permuted node field: (x, w, y, z)
        float4 r0, r1;
        r0.x = m0.x * f0.x + m0.y * f0.w + m0.z * f0.y + m0.w * f0.z;
        r0.y = m1.x * f0.x + m1.y * f0.w + m1.z * f0.y + m1.w * f0.z;
        r0.z = m2.x * f0.x + m2.y * f0.w + m2.z * f0.y + m2.w * f0.z;
        r0.w = m3.x * f0.x + m3.y * f0.w + m3.z * f0.y + m3.w * f0.z;

        r1.x = m0.x * f1.x + m0.y * f1.w + m0.z * f1.y + m0.w * f1.z;
        r1.y = m1.x * f1.x + m1.y * f1.w + m1.z * f1.y + m1.w * f1.z;
        r1.z = m2.x * f1.x + m2.y * f1.w + m2.z * f1.y + m2.w * f1.z;
        r1.w = m3.x * f1.x + m3.y * f1.w + m3.z * f1.y + m3.w * f1.z;

        __stcs(&out[p],  r0);
        __stcs(&out[pb], r1);
    }

    // Tail (at most one iteration per thread).
    if (p < total) {
        const int b = __ldg(&batch[p >> 3]);
        const float4 f = __ldg(&field[b]);
        float4 r;
        r.x = m0.x * f.x + m0.y * f.w + m0.z * f.y + m0.w * f.z;
        r.y = m1.x * f.x + m1.y * f.w + m1.z * f.y + m1.w * f.z;
        r.z = m2.x * f.x + m2.y * f.w + m2.z * f.y + m2.w * f.z;
        r.w = m3.x * f.x + m3.y * f.w + m3.z * f.y + m3.w * f.z;
        __stcs(&out[p], r);
    }
}

extern "C" void kernel_launch(void* const* d_in, const int* in_sizes, int n_in,
                              void* d_out, int out_size)
{
    const int*    batch  = (const int*)d_in[0];
    // d_in[1] = positions (unused by the reference output)
    const float4* field  = (const float4*)d_in[2];
    const float4* matrix = (const float4*)d_in[3];
    float4*       out    = (float4*)d_out;

    int n_nodes = in_sizes[0];

    const int block = 256;
    const int grid  = 148 * 8;   // persistent; stride multiple of 8

    dgto_kernel<<<grid, block>>>(batch, field, matrix, out, n_nodes);
}